// round 1
// baseline (speedup 1.0000x reference)
#include <cuda_runtime.h>
#include <math.h>
#include <stddef.h>

#define Nn   12288
#define Dd   128
#define DOUT 64
#define KNN  20
#define EE   (Nn*KNN)

// ---- scratch (static device allocations; no cudaMalloc anywhere) ----
__device__ float g_xn[Nn*Dd];                  // normalized x
__device__ float g_adj[(size_t)Nn*Nn];         // 604 MB cosine-sim matrix
__device__ float g_topv[EE];                   // top-20 values per row
__device__ int   g_topi[EE];                   // top-20 column indices per row
__device__ float g_deg[Nn];
__device__ float g_dis[Nn];
__device__ float g_hw1[Nn*Dd];                 // x @ W1
__device__ float g_hagg[Nn*Dd];                // aggregated layer-1 (then relu'd in place)
__device__ float g_hw2[Nn*DOUT];               // h @ W2

// ---------------------------------------------------------------------
// init: zero deg, seed h_agg with b1, seed out with b2 (scatters accumulate)
__global__ void k_init(const float* __restrict__ b1, const float* __restrict__ b2,
                       float* __restrict__ out) {
    int i = blockIdx.x*256 + threadIdx.x;
    if (i < Nn*Dd)   g_hagg[i] = b1[i & (Dd-1)];
    if (i < Nn*DOUT) out[i]    = b2[i & (DOUT-1)];
    if (i < Nn)      g_deg[i]  = 0.f;
}

// ---------------------------------------------------------------------
// row normalize: one warp per row (32 lanes x float4 = 128 floats)
__global__ void k_rownorm(const float* __restrict__ x) {
    int warp = threadIdx.x >> 5, lane = threadIdx.x & 31;
    int r = blockIdx.x*8 + warp;
    float4 v = ((const float4*)x)[r*(Dd/4) + lane];
    float ss = v.x*v.x + v.y*v.y + v.z*v.z + v.w*v.w;
    #pragma unroll
    for (int o = 16; o; o >>= 1) ss += __shfl_xor_sync(0xffffffffu, ss, o);
    float s = 1.f / fmaxf(sqrtf(ss), 1e-12f);
    float4 w = make_float4(v.x*s, v.y*s, v.z*s, v.w*s);
    ((float4*)g_xn)[r*(Dd/4) + lane] = w;
}

// ---------------------------------------------------------------------
// SYRK: adj = xn @ xn^T, upper-triangle tiles only, mirrored store.
// 128x128 block tile, BK=32, 256 threads, 8x8 microtile per thread.
__global__ void __launch_bounds__(256) k_syrk() {
    int bx = blockIdx.x, by = blockIdx.y;
    if (by > bx) return;                      // compute only by <= bx
    __shared__ float As[32][128];
    __shared__ float Bs[32][128];
    int tid = threadIdx.x;
    int tx = tid & 15, ty = tid >> 4;
    float acc[8][8];
    #pragma unroll
    for (int i = 0; i < 8; i++)
        #pragma unroll
        for (int j = 0; j < 8; j++) acc[i][j] = 0.f;

    int rb = by*128, cb = bx*128;
    for (int k0 = 0; k0 < Dd; k0 += 32) {
        #pragma unroll
        for (int t = 0; t < 4; t++) {
            int q   = tid + t*256;
            int row = q >> 3;
            int k4  = (q & 7)*4;
            float4 a = *(const float4*)&g_xn[(rb+row)*Dd + k0 + k4];
            As[k4+0][row] = a.x; As[k4+1][row] = a.y;
            As[k4+2][row] = a.z; As[k4+3][row] = a.w;
            float4 b = *(const float4*)&g_xn[(cb+row)*Dd + k0 + k4];
            Bs[k4+0][row] = b.x; Bs[k4+1][row] = b.y;
            Bs[k4+2][row] = b.z; Bs[k4+3][row] = b.w;
        }
        __syncthreads();
        #pragma unroll 4
        for (int kk = 0; kk < 32; kk++) {
            float rA[8], rB[8];
            *(float4*)&rA[0] = *(const float4*)&As[kk][ty*8];
            *(float4*)&rA[4] = *(const float4*)&As[kk][ty*8+4];
            *(float4*)&rB[0] = *(const float4*)&Bs[kk][tx*8];
            *(float4*)&rB[4] = *(const float4*)&Bs[kk][tx*8+4];
            #pragma unroll
            for (int i = 0; i < 8; i++)
                #pragma unroll
                for (int j = 0; j < 8; j++)
                    acc[i][j] += rA[i]*rB[j];
        }
        __syncthreads();
    }
    #pragma unroll
    for (int i = 0; i < 8; i++) {
        size_t base = (size_t)(rb + ty*8 + i)*Nn + cb + tx*8;
        *(float4*)&g_adj[base]   = make_float4(acc[i][0],acc[i][1],acc[i][2],acc[i][3]);
        *(float4*)&g_adj[base+4] = make_float4(acc[i][4],acc[i][5],acc[i][6],acc[i][7]);
    }
    if (bx != by) {
        #pragma unroll
        for (int j = 0; j < 8; j++) {
            size_t base = (size_t)(cb + tx*8 + j)*Nn + rb + ty*8;
            *(float4*)&g_adj[base]   = make_float4(acc[0][j],acc[1][j],acc[2][j],acc[3][j]);
            *(float4*)&g_adj[base+4] = make_float4(acc[4][j],acc[5][j],acc[6][j],acc[7][j]);
        }
    }
}

// ---------------------------------------------------------------------
// top-20 per row: one warp per row. Per-lane sorted top-20 over a strided
// subset (fast path = 1 compare vs register threshold), then 20 rounds of
// warp argmax merge. Also scatter-adds weights into deg[col].
__device__ __forceinline__ float topk_insert(float* lv, int* li, float v, int c) {
    int p = KNN-1;
    while (p > 0 && lv[p-1] < v) { lv[p] = lv[p-1]; li[p] = li[p-1]; p--; }
    lv[p] = v; li[p] = c;
    return lv[KNN-1];
}

__global__ void k_topk() {
    int warp = threadIdx.x >> 5, lane = threadIdx.x & 31;
    int r = blockIdx.x*8 + warp;
    float lv[KNN]; int li[KNN];
    #pragma unroll
    for (int k = 0; k < KNN; k++) { lv[k] = -INFINITY; li[k] = -1; }
    float thresh = -INFINITY;
    const float4* rowp = (const float4*)(g_adj + (size_t)r*Nn);
    for (int it = 0; it < Nn/128; it++) {
        float4 v = rowp[it*32 + lane];
        int cb = (it*32 + lane)*4;
        if (v.x > thresh) thresh = topk_insert(lv, li, v.x, cb+0);
        if (v.y > thresh) thresh = topk_insert(lv, li, v.y, cb+1);
        if (v.z > thresh) thresh = topk_insert(lv, li, v.z, cb+2);
        if (v.w > thresh) thresh = topk_insert(lv, li, v.w, cb+3);
    }
    // merge: 20 rounds of warp argmax over each lane's sorted list
    int pi = 0;
    for (int k = 0; k < KNN; k++) {
        float bv = (pi < KNN) ? lv[pi] : -INFINITY;
        int   bl = lane;
        #pragma unroll
        for (int o = 16; o; o >>= 1) {
            float ov = __shfl_xor_sync(0xffffffffu, bv, o);
            int   ol = __shfl_xor_sync(0xffffffffu, bl, o);
            if (ov > bv || (ov == bv && ol < bl)) { bv = ov; bl = ol; }
        }
        if (lane == bl) {
            g_topv[r*KNN + k] = lv[pi];
            g_topi[r*KNN + k] = li[pi];
            atomicAdd(&g_deg[li[pi]], lv[pi]);
            pi++;
        }
    }
}

// ---------------------------------------------------------------------
__global__ void k_dis() {
    int i = blockIdx.x*256 + threadIdx.x;
    if (i < Nn) {
        float dg = g_deg[i];
        g_dis[i] = (dg > 0.f) ? (1.f / sqrtf(fmaxf(dg, 1e-30f))) : 0.f;
    }
}

// ---------------------------------------------------------------------
// dense transform: C[n, M] = A[n, 128] @ B[128, M], B chunked through smem.
template<int MDIM>
__device__ __forceinline__ void gemm_body(const float* __restrict__ A,
                                          const float* __restrict__ B,
                                          float* __restrict__ C) {
    constexpr int TPR  = MDIM/32;       // threads per row
    constexpr int ROWS = 256/TPR;
    __shared__ float Bs[64][MDIM];
    int tid = threadIdx.x;
    int rr  = tid / TPR;
    int cc  = (tid % TPR)*32;
    int row = blockIdx.x*ROWS + rr;
    float acc[32];
    #pragma unroll
    for (int j = 0; j < 32; j++) acc[j] = 0.f;
    for (int kb = 0; kb < Dd; kb += 64) {
        #pragma unroll
        for (int t = 0; t < 64*MDIM/1024; t++) {
            int q = tid + t*256;
            int k = q/(MDIM/4), c = (q % (MDIM/4))*4;
            *(float4*)&Bs[k][c] = *(const float4*)&B[(kb+k)*MDIM + c];
        }
        __syncthreads();
        #pragma unroll 8
        for (int k = 0; k < 64; k++) {
            float a = A[row*Dd + kb + k];
            #pragma unroll
            for (int j = 0; j < 32; j += 4) {
                float4 b = *(const float4*)&Bs[k][cc+j];
                acc[j+0] += a*b.x; acc[j+1] += a*b.y;
                acc[j+2] += a*b.z; acc[j+3] += a*b.w;
            }
        }
        __syncthreads();
    }
    #pragma unroll
    for (int j = 0; j < 32; j += 4)
        *(float4*)&C[row*MDIM + cc + j] =
            make_float4(acc[j],acc[j+1],acc[j+2],acc[j+3]);
}

__global__ void __launch_bounds__(256) k_gemm1(const float* __restrict__ x,
                                               const float* __restrict__ W1) {
    gemm_body<Dd>(x, W1, g_hw1);
}
__global__ void __launch_bounds__(256) k_gemm2(const float* __restrict__ W2) {
    gemm_body<DOUT>(g_hagg, W2, g_hw2);
}

// ---------------------------------------------------------------------
__global__ void k_relu() {
    int i = blockIdx.x*256 + threadIdx.x;
    if (i < Nn*Dd) g_hagg[i] = fmaxf(g_hagg[i], 0.f);
}

// ---------------------------------------------------------------------
// edge scatter: one warp per edge; dst[c] += dis[r]*w*dis[c] * src[r]
template<int F>
__device__ __forceinline__ void scatter_body(const float* __restrict__ src,
                                             float* __restrict__ dst) {
    int gw   = (blockIdx.x*256 + threadIdx.x) >> 5;
    int lane = threadIdx.x & 31;
    if (gw >= EE) return;
    int r = gw / KNN;
    int c = g_topi[gw];
    float nrm = g_dis[r] * g_topv[gw] * g_dis[c];
    constexpr int PER = F/32;
    const float* s = src + r*F + lane*PER;
    float*       d = dst + c*F + lane*PER;
    #pragma unroll
    for (int t = 0; t < PER; t++) atomicAdd(d + t, nrm * s[t]);
}

__global__ void k_scatter1() { scatter_body<Dd>(g_hw1, g_hagg); }
__global__ void k_scatter2(float* __restrict__ out) { scatter_body<DOUT>(g_hw2, out); }

// ---------------------------------------------------------------------
extern "C" void kernel_launch(void* const* d_in, const int* in_sizes, int n_in,
                              void* d_out, int out_size) {
    const float* x  = (const float*)d_in[0];
    const float* W1 = (const float*)d_in[1];
    const float* b1 = (const float*)d_in[2];
    const float* W2 = (const float*)d_in[3];
    const float* b2 = (const float*)d_in[4];
    float* out = (float*)d_out;

    k_init    <<<(Nn*Dd)/256, 256>>>(b1, b2, out);
    k_rownorm <<<Nn/8, 256>>>(x);
    k_syrk    <<<dim3(96, 96), 256>>>();
    k_topk    <<<Nn/8, 256>>>();
    k_dis     <<<(Nn+255)/256, 256>>>();
    k_gemm1   <<<Nn/64, 256>>>(x, W1);
    k_scatter1<<<(EE*32)/256, 256>>>();
    k_relu    <<<(Nn*Dd)/256, 256>>>();
    k_gemm2   <<<Nn/128, 256>>>(W2);
    k_scatter2<<<(EE*32)/256, 256>>>(out);
}